// round 7
// baseline (speedup 1.0000x reference)
#include <cuda_runtime.h>
#include <stdint.h>

// BurgerDissipativeLossOperator
//   du[i]  = (u1[i]*A[i] - B[i]) / max(cnt[i],1)   A=Σ 1/len, B=Σ u1[src]/len
//   d2u[i] = (du[i]*A[i] - C[i]) / max(cnt[i],1)   C=Σ du[src]/len
//   loss   = ((u0-u1)/dt + du*u1 - MU*d2u) * mask
//
// V = Σ (256 + 1/len) = 256*cnt + A packs cnt+A into one float ->
// pass 1 is a single red.global.add.v2.f32 {V,B} per edge.
// 8 edges per thread, loads batched before reductions for high MLP.

#define N_NODES 4000000
#define N_EDGES 8000000
#define INV_DT  100.0f
#define MU      0.01f
#define K_PACK  256.0f
#define INV_K   0.00390625f   // 1/256

__device__ float2 g_acc[N_NODES];   // {V = 256*cnt + A, B}
__device__ float  g_C[N_NODES];     // Σ du[src]/len
__device__ float  g_du[N_NODES];

// ---------------------------------------------------------------------------
// init (4 nodes/thread): pure zero-fill of accumulators
__global__ void k_zero() {
    int t = blockIdx.x * blockDim.x + threadIdx.x;
    if (t >= N_NODES / 4) return;
    float4 z = make_float4(0.f, 0.f, 0.f, 0.f);
    ((float4*)g_acc)[t * 2 + 0] = z;
    ((float4*)g_acc)[t * 2 + 1] = z;
    ((float4*)g_C)[t] = z;
}

// pass 1 (8 edges/thread): red.v2 {V += 256 + 1/len, B += u1[s]/len}
__global__ void k_edge1(const int4* __restrict__ ei_s,
                        const int4* __restrict__ ei_d,
                        const float4* __restrict__ attr,
                        const float* __restrict__ x_t1) {
    int t = blockIdx.x * blockDim.x + threadIdx.x;
    if (t >= N_EDGES / 8) return;
    int4   sa = __ldcs(&ei_s[t * 2 + 0]);
    int4   sb = __ldcs(&ei_s[t * 2 + 1]);
    int4   da = __ldcs(&ei_d[t * 2 + 0]);
    int4   db = __ldcs(&ei_d[t * 2 + 1]);
    float4 la = __ldcs(&attr[t * 2 + 0]);
    float4 lb = __ldcs(&attr[t * 2 + 1]);

    float u0 = __ldg(&x_t1[2 * sa.x]);
    float u1 = __ldg(&x_t1[2 * sa.y]);
    float u2 = __ldg(&x_t1[2 * sa.z]);
    float u3 = __ldg(&x_t1[2 * sa.w]);
    float u4 = __ldg(&x_t1[2 * sb.x]);
    float u5 = __ldg(&x_t1[2 * sb.y]);
    float u6 = __ldg(&x_t1[2 * sb.z]);
    float u7 = __ldg(&x_t1[2 * sb.w]);

    float r0 = 1.0f / la.x, r1 = 1.0f / la.y, r2 = 1.0f / la.z, r3 = 1.0f / la.w;
    float r4 = 1.0f / lb.x, r5 = 1.0f / lb.y, r6 = 1.0f / lb.z, r7 = 1.0f / lb.w;

    #define RED2(dn, rn, un) \
        asm volatile("red.global.add.v2.f32 [%0], {%1, %2};" \
                     :: "l"(&g_acc[dn]), "f"(K_PACK + rn), "f"((un) * (rn)) : "memory")
    RED2(da.x, r0, u0); RED2(da.y, r1, u1); RED2(da.z, r2, u2); RED2(da.w, r3, u3);
    RED2(db.x, r4, u4); RED2(db.y, r5, u5); RED2(db.z, r6, u6); RED2(db.w, r7, u7);
    #undef RED2
}

// node pass (4 nodes/thread): unpack cnt/A, du = (u1*A - B) / max(cnt,1)
__device__ __forceinline__ float node_du(float V, float B, float u1) {
    float k = floorf(V * INV_K);          // cnt
    float A = V - K_PACK * k;
    float c = fmaxf(k, 1.0f);
    return (u1 * A - B) / c;
}

__global__ void k_du(const float4* __restrict__ x_t1) {
    int t = blockIdx.x * blockDim.x + threadIdx.x;
    if (t >= N_NODES / 4) return;
    float4 xa = __ldg(&x_t1[t * 2 + 0]);   // u1[4t], v, u1[4t+1], v
    float4 xb = __ldg(&x_t1[t * 2 + 1]);   // u1[4t+2], v, u1[4t+3], v
    float4 p0 = ((const float4*)g_acc)[t * 2 + 0];  // {V0,B0,V1,B1}
    float4 p1 = ((const float4*)g_acc)[t * 2 + 1];  // {V2,B2,V3,B3}
    float4 du;
    du.x = node_du(p0.x, p0.y, xa.x);
    du.y = node_du(p0.z, p0.w, xa.z);
    du.z = node_du(p1.x, p1.y, xb.x);
    du.w = node_du(p1.z, p1.w, xb.z);
    ((float4*)g_du)[t] = du;
}

// pass 2 (8 edges/thread): C[d] += du[s]/len
__global__ void k_edge2(const int4* __restrict__ ei_s,
                        const int4* __restrict__ ei_d,
                        const float4* __restrict__ attr) {
    int t = blockIdx.x * blockDim.x + threadIdx.x;
    if (t >= N_EDGES / 8) return;
    int4   sa = __ldcs(&ei_s[t * 2 + 0]);
    int4   sb = __ldcs(&ei_s[t * 2 + 1]);
    int4   da = __ldcs(&ei_d[t * 2 + 0]);
    int4   db = __ldcs(&ei_d[t * 2 + 1]);
    float4 la = __ldcs(&attr[t * 2 + 0]);
    float4 lb = __ldcs(&attr[t * 2 + 1]);

    float d0 = __ldg(&g_du[sa.x]);
    float d1 = __ldg(&g_du[sa.y]);
    float d2 = __ldg(&g_du[sa.z]);
    float d3 = __ldg(&g_du[sa.w]);
    float d4 = __ldg(&g_du[sb.x]);
    float d5 = __ldg(&g_du[sb.y]);
    float d6 = __ldg(&g_du[sb.z]);
    float d7 = __ldg(&g_du[sb.w]);

    atomicAdd(&g_C[da.x], d0 / la.x);
    atomicAdd(&g_C[da.y], d1 / la.y);
    atomicAdd(&g_C[da.z], d2 / la.z);
    atomicAdd(&g_C[da.w], d3 / la.w);
    atomicAdd(&g_C[db.x], d4 / lb.x);
    atomicAdd(&g_C[db.y], d5 / lb.y);
    atomicAdd(&g_C[db.z], d6 / lb.z);
    atomicAdd(&g_C[db.w], d7 / lb.w);
}

// epilogue (4 nodes/thread)
__device__ __forceinline__ float node_loss(float V, float C, float du,
                                           float u0, float u1, float m) {
    float k = floorf(V * INV_K);
    float A = V - K_PACK * k;
    float c = fmaxf(k, 1.0f);
    float d2u = (du * A - C) / c;
    return ((u0 - u1) * INV_DT + du * u1 - MU * d2u) * m;
}

__global__ void k_final(const float4* __restrict__ x_t,
                        const float4* __restrict__ x_t1,
                        const float4* __restrict__ mask,
                        float4* __restrict__ out) {
    int t = blockIdx.x * blockDim.x + threadIdx.x;
    if (t >= N_NODES / 4) return;
    float4 p0 = ((const float4*)g_acc)[t * 2 + 0];
    float4 p1 = ((const float4*)g_acc)[t * 2 + 1];
    float4 du = ((const float4*)g_du)[t];
    float4 C  = ((const float4*)g_C)[t];
    float4 ya = __ldg(&x_t1[t * 2 + 0]);
    float4 yb = __ldg(&x_t1[t * 2 + 1]);
    float4 xa = __ldcs(&x_t[t * 2 + 0]);
    float4 xb = __ldcs(&x_t[t * 2 + 1]);
    float4 m  = __ldcs(&mask[t]);

    float4 o;
    o.x = node_loss(p0.x, C.x, du.x, xa.x, ya.x, m.x);
    o.y = node_loss(p0.z, C.y, du.y, xa.z, ya.z, m.y);
    o.z = node_loss(p1.x, C.z, du.z, xb.x, yb.x, m.z);
    o.w = node_loss(p1.z, C.w, du.w, xb.z, yb.z, m.w);
    out[t] = o;
}

// ---------------------------------------------------------------------------
extern "C" void kernel_launch(void* const* d_in, const int* in_sizes, int n_in,
                              void* d_out, int out_size) {
    const float4* x_t   = (const float4*)d_in[0];
    const float*  x_t1  = (const float*)d_in[1];
    const float4* x_t1v = (const float4*)d_in[1];
    const int*    ei    = (const int*)d_in[2];
    const float4* attr  = (const float4*)d_in[3];
    const float4* mask  = (const float4*)d_in[4];
    float4*       out   = (float4*)d_out;

    const int4* ei_s = (const int4*)ei;
    const int4* ei_d = (const int4*)(ei + N_EDGES);

    const int TB = 256;
    const int gn = (N_NODES / 4 + TB - 1) / TB;
    const int ge = (N_EDGES / 8 + TB - 1) / TB;

    k_zero <<<gn, TB>>>();
    k_edge1<<<ge, TB>>>(ei_s, ei_d, attr, x_t1);
    k_du   <<<gn, TB>>>(x_t1v);
    k_edge2<<<ge, TB>>>(ei_s, ei_d, attr);
    k_final<<<gn, TB>>>(x_t, x_t1v, mask, out);
}

// round 9
// speedup vs baseline: 1.0402x; 1.0402x over previous
#include <cuda_runtime.h>
#include <stdint.h>

// BurgerDissipativeLossOperator
//   du[i]  = (u1[i]*A[i] - B[i]) / max(cnt[i],1)   A=Σ 1/len, B=Σ u1[src]/len
//   d2u[i] = (du[i]*A[i] - C[i]) / max(cnt[i],1)   C=Σ du[src]/len
//   loss   = ((u0-u1)/dt + du*u1 - MU*d2u) * mask
//
// V = Σ (256 + 1/len) = 256*cnt + A packs cnt+A into one float ->
// pass 1 is a single red.global.add.v2.f32 {V,B} per edge (8B RMW).
// 4 edges / 4 nodes per thread (R6 config). Streams use __ldcs
// (evict-first); random gathers use createpolicy + L2::cache_hint
// (evict_last) so the 16MB hot arrays stay L2-resident.

#define N_NODES 4000000
#define N_EDGES 8000000
#define INV_DT  100.0f
#define MU      0.01f
#define K_PACK  256.0f
#define INV_K   0.00390625f   // 1/256

__device__ float2 g_acc[N_NODES];   // {V = 256*cnt + A, B}
__device__ float  g_C[N_NODES];     // Σ du[src]/len
__device__ float  g_du[N_NODES];
__device__ float  g_u1[N_NODES];    // compacted x_t1[:,0]

// evict-last policy handle (per-thread, cheap)
__device__ __forceinline__ uint64_t mk_policy() {
    uint64_t pol;
    asm volatile("createpolicy.fractional.L2::evict_last.b64 %0, 1.0;" : "=l"(pol));
    return pol;
}

// random gather with L2 evict-last cache hint (keep hot array resident)
__device__ __forceinline__ float ld_hot(const float* p, uint64_t pol) {
    float v;
    asm volatile("ld.global.nc.L2::cache_hint.f32 %0, [%1], %2;"
                 : "=f"(v) : "l"(p), "l"(pol));
    return v;
}

// ---------------------------------------------------------------------------
// init (4 nodes/thread): zero accumulators, compact u1
__global__ void __launch_bounds__(256) k_init(const float4* __restrict__ x_t1) {
    int t = blockIdx.x * blockDim.x + threadIdx.x;
    if (t >= N_NODES / 4) return;
    float4 z = make_float4(0.f, 0.f, 0.f, 0.f);
    ((float4*)g_acc)[t * 2 + 0] = z;
    ((float4*)g_acc)[t * 2 + 1] = z;
    ((float4*)g_C)[t] = z;
    float4 a = __ldcs(&x_t1[t * 2 + 0]);
    float4 b = __ldcs(&x_t1[t * 2 + 1]);
    ((float4*)g_u1)[t] = make_float4(a.x, a.z, b.x, b.z);
}

// pass 1 (4 edges/thread): red.v2 {V += 256 + 1/len, B += u1[s]/len}
__global__ void __launch_bounds__(256) k_edge1(const int4* __restrict__ ei_s,
                                               const int4* __restrict__ ei_d,
                                               const float4* __restrict__ attr) {
    int t = blockIdx.x * blockDim.x + threadIdx.x;
    if (t >= N_EDGES / 4) return;
    int4   s4 = __ldcs(&ei_s[t]);
    int4   d4 = __ldcs(&ei_d[t]);
    float4 l4 = __ldcs(&attr[t]);

    uint64_t pol = mk_policy();
    float u0 = ld_hot(&g_u1[s4.x], pol);
    float u1 = ld_hot(&g_u1[s4.y], pol);
    float u2 = ld_hot(&g_u1[s4.z], pol);
    float u3 = ld_hot(&g_u1[s4.w], pol);

    float r0 = 1.0f / l4.x, r1 = 1.0f / l4.y, r2 = 1.0f / l4.z, r3 = 1.0f / l4.w;

    asm volatile("red.global.add.v2.f32 [%0], {%1, %2};"
                 :: "l"(&g_acc[d4.x]), "f"(K_PACK + r0), "f"(u0 * r0) : "memory");
    asm volatile("red.global.add.v2.f32 [%0], {%1, %2};"
                 :: "l"(&g_acc[d4.y]), "f"(K_PACK + r1), "f"(u1 * r1) : "memory");
    asm volatile("red.global.add.v2.f32 [%0], {%1, %2};"
                 :: "l"(&g_acc[d4.z]), "f"(K_PACK + r2), "f"(u2 * r2) : "memory");
    asm volatile("red.global.add.v2.f32 [%0], {%1, %2};"
                 :: "l"(&g_acc[d4.w]), "f"(K_PACK + r3), "f"(u3 * r3) : "memory");
}

// node pass (4 nodes/thread): unpack cnt/A, du = (u1*A - B) / max(cnt,1)
__device__ __forceinline__ float node_du(float V, float B, float u1) {
    float k = floorf(V * INV_K);          // cnt
    float A = V - K_PACK * k;
    float c = fmaxf(k, 1.0f);
    return (u1 * A - B) / c;
}

__global__ void __launch_bounds__(256) k_du() {
    int t = blockIdx.x * blockDim.x + threadIdx.x;
    if (t >= N_NODES / 4) return;
    float4 u  = ((const float4*)g_u1)[t];
    float4 p0 = ((const float4*)g_acc)[t * 2 + 0];  // {V0,B0,V1,B1}
    float4 p1 = ((const float4*)g_acc)[t * 2 + 1];  // {V2,B2,V3,B3}
    float4 du;
    du.x = node_du(p0.x, p0.y, u.x);
    du.y = node_du(p0.z, p0.w, u.y);
    du.z = node_du(p1.x, p1.y, u.z);
    du.w = node_du(p1.z, p1.w, u.w);
    ((float4*)g_du)[t] = du;
}

// pass 2 (4 edges/thread): C[d] += du[s]/len
__global__ void __launch_bounds__(256) k_edge2(const int4* __restrict__ ei_s,
                                               const int4* __restrict__ ei_d,
                                               const float4* __restrict__ attr) {
    int t = blockIdx.x * blockDim.x + threadIdx.x;
    if (t >= N_EDGES / 4) return;
    int4   s4 = __ldcs(&ei_s[t]);
    int4   d4 = __ldcs(&ei_d[t]);
    float4 l4 = __ldcs(&attr[t]);

    uint64_t pol = mk_policy();
    float d0 = ld_hot(&g_du[s4.x], pol);
    float d1 = ld_hot(&g_du[s4.y], pol);
    float d2 = ld_hot(&g_du[s4.z], pol);
    float d3 = ld_hot(&g_du[s4.w], pol);

    atomicAdd(&g_C[d4.x], d0 / l4.x);
    atomicAdd(&g_C[d4.y], d1 / l4.y);
    atomicAdd(&g_C[d4.z], d2 / l4.z);
    atomicAdd(&g_C[d4.w], d3 / l4.w);
}

// epilogue (4 nodes/thread)
__device__ __forceinline__ float node_loss(float V, float C, float du,
                                           float u0, float u1, float m) {
    float k = floorf(V * INV_K);
    float A = V - K_PACK * k;
    float c = fmaxf(k, 1.0f);
    float d2u = (du * A - C) / c;
    return ((u0 - u1) * INV_DT + du * u1 - MU * d2u) * m;
}

__global__ void __launch_bounds__(256) k_final(const float4* __restrict__ x_t,
                                               const float4* __restrict__ mask,
                                               float4* __restrict__ out) {
    int t = blockIdx.x * blockDim.x + threadIdx.x;
    if (t >= N_NODES / 4) return;
    float4 p0 = ((const float4*)g_acc)[t * 2 + 0];
    float4 p1 = ((const float4*)g_acc)[t * 2 + 1];
    float4 du = ((const float4*)g_du)[t];
    float4 C  = ((const float4*)g_C)[t];
    float4 u1 = ((const float4*)g_u1)[t];
    float4 xa = __ldcs(&x_t[t * 2 + 0]);
    float4 xb = __ldcs(&x_t[t * 2 + 1]);
    float4 m  = __ldcs(&mask[t]);

    float4 o;
    o.x = node_loss(p0.x, C.x, du.x, xa.x, u1.x, m.x);
    o.y = node_loss(p0.z, C.y, du.y, xa.z, u1.y, m.y);
    o.z = node_loss(p1.x, C.z, du.z, xb.x, u1.z, m.z);
    o.w = node_loss(p1.z, C.w, du.w, xb.z, u1.w, m.w);
    out[t] = o;
}

// ---------------------------------------------------------------------------
extern "C" void kernel_launch(void* const* d_in, const int* in_sizes, int n_in,
                              void* d_out, int out_size) {
    const float4* x_t  = (const float4*)d_in[0];
    const float4* x_t1 = (const float4*)d_in[1];
    const int*    ei   = (const int*)d_in[2];
    const float4* attr = (const float4*)d_in[3];
    const float4* mask = (const float4*)d_in[4];
    float4*       out  = (float4*)d_out;

    const int4* ei_s = (const int4*)ei;
    const int4* ei_d = (const int4*)(ei + N_EDGES);

    const int TB = 256;
    const int gn = (N_NODES / 4 + TB - 1) / TB;
    const int ge = (N_EDGES / 4 + TB - 1) / TB;

    k_init <<<gn, TB>>>(x_t1);
    k_edge1<<<ge, TB>>>(ei_s, ei_d, attr);
    k_du   <<<gn, TB>>>();
    k_edge2<<<ge, TB>>>(ei_s, ei_d, attr);
    k_final<<<gn, TB>>>(x_t, mask, out);
}